// round 1
// baseline (speedup 1.0000x reference)
#include <cuda_runtime.h>
#include <cuda_bf16.h>

// Problem constants
#define C_DIM  256
#define L_DIM  4096      // 64*64
#define LM_DIM 36864     // 192*192 = 9 * L_DIM
#define B_DIM  4

// Scratch (allocation-free rule: __device__ globals)
__device__ float g_M[C_DIM * C_DIM];                 // M = W1a @ W2b^T   (256 KB)
__device__ float g_U[B_DIM * C_DIM * L_DIM];         // u^T per batch: [C][L]  (16 MB)

// ---------------- f32x2 helpers (full-rate fp32 FMA on Blackwell) ----------------
__device__ __forceinline__ unsigned long long fma2(unsigned long long a,
                                                   unsigned long long b,
                                                   unsigned long long c) {
    unsigned long long d;
    asm("fma.rn.f32x2 %0, %1, %2, %3;" : "=l"(d) : "l"(a), "l"(b), "l"(c));
    return d;
}
__device__ __forceinline__ unsigned long long dup2(float x) {
    unsigned long long d;
    unsigned int xi = __float_as_uint(x);
    asm("mov.b64 %0, {%1, %1};" : "=l"(d) : "r"(xi));
    return d;
}
__device__ __forceinline__ float lo32(unsigned long long v) {
    return __uint_as_float((unsigned int)(v & 0xffffffffull));
}
__device__ __forceinline__ float hi32(unsigned long long v) {
    return __uint_as_float((unsigned int)(v >> 32));
}

// ---------------- Kernel 1: M[c1][c2] = sum_c W1[c1][c] * W2[c2][256+c] ----------------
// Tiny (16M MAC). 32x32 output tiles, 64-deep k chunks staged in smem.
__global__ __launch_bounds__(256) void k1_M(const float* __restrict__ W1,
                                            const float* __restrict__ W2) {
    __shared__ __align__(16) float A[32][68];
    __shared__ __align__(16) float Bt[32][68];
    const int tid  = threadIdx.x;
    const int c1_0 = blockIdx.y * 32;
    const int c2_0 = blockIdx.x * 32;
    const int ty = tid >> 4, tx = tid & 15;
    const int lr = tid >> 3;          // 0..31
    const int lc = (tid & 7) * 8;     // 0..56

    float acc00 = 0.f, acc01 = 0.f, acc10 = 0.f, acc11 = 0.f;

    for (int kk = 0; kk < 256; kk += 64) {
        float4 a0 = *(const float4*)&W1[(c1_0 + lr) * 768 + kk + lc];
        float4 a1 = *(const float4*)&W1[(c1_0 + lr) * 768 + kk + lc + 4];
        float4 b0 = *(const float4*)&W2[(c2_0 + lr) * 768 + 256 + kk + lc];
        float4 b1 = *(const float4*)&W2[(c2_0 + lr) * 768 + 256 + kk + lc + 4];
        __syncthreads();
        *(float4*)&A[lr][lc]      = a0;
        *(float4*)&A[lr][lc + 4]  = a1;
        *(float4*)&Bt[lr][lc]     = b0;
        *(float4*)&Bt[lr][lc + 4] = b1;
        __syncthreads();
        #pragma unroll
        for (int k = 0; k < 64; ++k) {
            float x0 = A[ty * 2][k],  x1 = A[ty * 2 + 1][k];
            float y0 = Bt[tx * 2][k], y1 = Bt[tx * 2 + 1][k];
            acc00 += x0 * y0; acc01 += x0 * y1;
            acc10 += x1 * y0; acc11 += x1 * y1;
        }
    }
    g_M[(c1_0 + ty * 2)     * 256 + c2_0 + tx * 2]     = acc00;
    g_M[(c1_0 + ty * 2)     * 256 + c2_0 + tx * 2 + 1] = acc01;
    g_M[(c1_0 + ty * 2 + 1) * 256 + c2_0 + tx * 2]     = acc10;
    g_M[(c1_0 + ty * 2 + 1) * 256 + c2_0 + tx * 2 + 1] = acc11;
}

// ---------------- Kernel 2: U[b][c2][l] = sum_c1 M[c1][c2] * HSI[b][c1][l] ----------------
// Per batch: U^T (256 x 4096) = M^T @ HSI_b. 64(c2) x 128(l) tiles, k-chunk 32.
// f32x2 accumulation: pairs along c2 (LDS.64 broadcast), HSI scalar duplicated.
__global__ __launch_bounds__(256) void k2_U(const float* __restrict__ HSI) {
    __shared__ __align__(16) float Ms[32][64];
    __shared__ __align__(16) float Hs[32][128];
    const int tid  = threadIdx.x;
    const int b    = blockIdx.z;
    const int c2_0 = blockIdx.y * 64;
    const int l0   = blockIdx.x * 128;
    const float* Hb = HSI + (size_t)b * C_DIM * L_DIM;
    float*       Ub = g_U + (size_t)b * C_DIM * L_DIM;
    const int ty = tid >> 5, tx = tid & 31;

    unsigned long long acc[4][4];
    #pragma unroll
    for (int i = 0; i < 4; ++i)
        #pragma unroll
        for (int j = 0; j < 4; ++j) acc[i][j] = 0ull;

    const int mlr = tid >> 4;           // 0..15
    const int mlc = (tid & 15) * 4;     // 0..60
    const int hlr = tid >> 5;           // 0..7
    const int hlc = (tid & 31) * 4;     // 0..124

    for (int kk = 0; kk < 256; kk += 32) {
        float4 m0 = *(const float4*)&g_M[(kk + mlr)      * 256 + c2_0 + mlc];
        float4 m1 = *(const float4*)&g_M[(kk + mlr + 16) * 256 + c2_0 + mlc];
        float4 h0 = *(const float4*)&Hb[(size_t)(kk + hlr)      * L_DIM + l0 + hlc];
        float4 h1 = *(const float4*)&Hb[(size_t)(kk + hlr + 8)  * L_DIM + l0 + hlc];
        float4 h2 = *(const float4*)&Hb[(size_t)(kk + hlr + 16) * L_DIM + l0 + hlc];
        float4 h3 = *(const float4*)&Hb[(size_t)(kk + hlr + 24) * L_DIM + l0 + hlc];
        __syncthreads();
        *(float4*)&Ms[mlr][mlc]      = m0;
        *(float4*)&Ms[mlr + 16][mlc] = m1;
        *(float4*)&Hs[hlr][hlc]      = h0;
        *(float4*)&Hs[hlr + 8][hlc]  = h1;
        *(float4*)&Hs[hlr + 16][hlc] = h2;
        *(float4*)&Hs[hlr + 24][hlc] = h3;
        __syncthreads();
        #pragma unroll
        for (int k = 0; k < 32; ++k) {
            unsigned long long a0 = *(const unsigned long long*)&Ms[k][ty * 8];
            unsigned long long a1 = *(const unsigned long long*)&Ms[k][ty * 8 + 2];
            unsigned long long a2 = *(const unsigned long long*)&Ms[k][ty * 8 + 4];
            unsigned long long a3 = *(const unsigned long long*)&Ms[k][ty * 8 + 6];
            float4 h = *(const float4*)&Hs[k][tx * 4];
            unsigned long long hd0 = dup2(h.x), hd1 = dup2(h.y);
            unsigned long long hd2 = dup2(h.z), hd3 = dup2(h.w);
            acc[0][0] = fma2(a0, hd0, acc[0][0]);
            acc[0][1] = fma2(a0, hd1, acc[0][1]);
            acc[0][2] = fma2(a0, hd2, acc[0][2]);
            acc[0][3] = fma2(a0, hd3, acc[0][3]);
            acc[1][0] = fma2(a1, hd0, acc[1][0]);
            acc[1][1] = fma2(a1, hd1, acc[1][1]);
            acc[1][2] = fma2(a1, hd2, acc[1][2]);
            acc[1][3] = fma2(a1, hd3, acc[1][3]);
            acc[2][0] = fma2(a2, hd0, acc[2][0]);
            acc[2][1] = fma2(a2, hd1, acc[2][1]);
            acc[2][2] = fma2(a2, hd2, acc[2][2]);
            acc[2][3] = fma2(a2, hd3, acc[2][3]);
            acc[3][0] = fma2(a3, hd0, acc[3][0]);
            acc[3][1] = fma2(a3, hd1, acc[3][1]);
            acc[3][2] = fma2(a3, hd2, acc[3][2]);
            acc[3][3] = fma2(a3, hd3, acc[3][3]);
        }
    }
    #pragma unroll
    for (int i = 0; i < 4; ++i) {
        int r0 = c2_0 + ty * 8 + 2 * i;
        float4 v0 = make_float4(lo32(acc[i][0]), lo32(acc[i][1]), lo32(acc[i][2]), lo32(acc[i][3]));
        float4 v1 = make_float4(hi32(acc[i][0]), hi32(acc[i][1]), hi32(acc[i][2]), hi32(acc[i][3]));
        *(float4*)&Ub[(size_t)r0       * L_DIM + l0 + tx * 4] = v0;
        *(float4*)&Ub[(size_t)(r0 + 1) * L_DIM + l0 + tx * 4] = v1;
    }
}

// ---------------- Kernel 3: s[b,l,n] = sum_c2 U[b][c2][l] * MSI[b][c2][9l+n]; argmax -> offsets ----------------
// One block: 32 l values = 288 m values, 288 threads (1 m each). HBM-bound on MSI stream.
__global__ __launch_bounds__(288) void k3_attn(const float* __restrict__ MSI,
                                               float* __restrict__ out) {
    __shared__ __align__(16) float us[256][33];  // padded: conflict-free for us[c2][t/9]
    __shared__ float sc[288];
    const int t  = threadIdx.x;
    const int b  = blockIdx.y;
    const int l0 = blockIdx.x * 32;
    const int m0 = blockIdx.x * 288;
    const float* Mb = MSI + (size_t)b * C_DIM * LM_DIM;
    const float* Ub = g_U + (size_t)b * C_DIM * L_DIM;

    // stage the 32-wide u slice: us[c2][l_local]
    for (int i = t; i < 256 * 32; i += 288) {
        int c2 = i >> 5, l = i & 31;
        us[c2][l] = Ub[(size_t)c2 * L_DIM + l0 + l];
    }
    __syncthreads();

    const int m  = m0 + t;
    const int ll = t / 9;
    const float* mp = Mb + m;
    float acc = 0.f;
    #pragma unroll 8
    for (int c2 = 0; c2 < 256; ++c2)
        acc += us[c2][ll] * mp[c2 * LM_DIM];
    sc[t] = acc;
    __syncthreads();

    if (t < 32) {
        float best = sc[t * 9];
        int bn = 0;
        #pragma unroll
        for (int j = 1; j < 9; ++j) {
            float v = sc[t * 9 + j];
            if (v > best) { best = v; bn = j; }   // strict > keeps first max (jnp.argmax)
        }
        float2 o = make_float2((float)(bn / 3) - 1.f, (float)(bn % 3) - 1.f);
        *(float2*)&out[(size_t)(b * L_DIM + l0 + t) * 2] = o;
    }
}

// ---------------- launch ----------------
extern "C" void kernel_launch(void* const* d_in, const int* in_sizes, int n_in,
                              void* d_out, int out_size) {
    // metadata order: x, y, HSI_Patch, MSI_Patch2, W_qkv1, W_qkv2
    const float* HSI = (const float*)d_in[2];
    const float* MSI = (const float*)d_in[3];
    const float* W1  = (const float*)d_in[4];
    const float* W2  = (const float*)d_in[5];
    float* out = (float*)d_out;

    k1_M<<<dim3(8, 8), 256>>>(W1, W2);
    k2_U<<<dim3(32, 4, 4), 256>>>(HSI);
    k3_attn<<<dim3(128, 4), 288>>>(MSI, out);
}

// round 3
// speedup vs baseline: 1.1277x; 1.1277x over previous
#include <cuda_runtime.h>
#include <cstdint>

#define C_DIM  256
#define L_DIM  4096
#define LM_DIM 36864
#define B_DIM  4

// Scratch (__device__ globals per allocation-free rule)
__device__ float g_M[C_DIM * C_DIM];             // M[c1][c2] = sum_c W1[c1][c]*W2[c2][256+c]
__device__ float g_U[B_DIM * C_DIM * L_DIM];     // U[b][c2][l]

// ---------------- helpers ----------------
__device__ __forceinline__ uint32_t smem_u32(const void* p) {
    uint32_t a;
    asm("{ .reg .u64 t; cvta.to.shared.u64 t, %1; cvt.u32.u64 %0, t; }" : "=r"(a) : "l"(p));
    return a;
}
__device__ __forceinline__ void cp16(uint32_t dst, const void* src) {
    asm volatile("cp.async.cg.shared.global [%0], [%1], 16;" :: "r"(dst), "l"(src) : "memory");
}
__device__ __forceinline__ void cp_commit() {
    asm volatile("cp.async.commit_group;" ::: "memory");
}
template <int N>
__device__ __forceinline__ void cp_wait() {
    asm volatile("cp.async.wait_group %0;" :: "n"(N) : "memory");
}
__device__ __forceinline__ uint32_t tf32_hi(float v) {
    uint32_t h;
    asm("cvt.rna.tf32.f32 %0, %1;" : "=r"(h) : "f"(v));
    return h;
}
__device__ __forceinline__ uint32_t tf32_lo(float v, uint32_t hi) {
    float l = v - __uint_as_float(hi);
    uint32_t r;
    asm("cvt.rna.tf32.f32 %0, %1;" : "=r"(r) : "f"(l));
    return r;
}
__device__ __forceinline__ void mma8(float* d, const uint32_t* a, const uint32_t* b) {
    asm volatile(
        "mma.sync.aligned.m16n8k8.row.col.f32.tf32.tf32.f32 "
        "{%0,%1,%2,%3}, {%4,%5,%6,%7}, {%8,%9}, {%0,%1,%2,%3};"
        : "+f"(d[0]), "+f"(d[1]), "+f"(d[2]), "+f"(d[3])
        : "r"(a[0]), "r"(a[1]), "r"(a[2]), "r"(a[3]), "r"(b[0]), "r"(b[1]));
}

// ---------------- Kernel 1: M[c1][c2], k-split + atomicAdd ----------------
__global__ __launch_bounds__(256) void k1_M(const float* __restrict__ W1,
                                            const float* __restrict__ W2) {
    __shared__ float A[32][65];   // [c1_local][k]
    __shared__ float Bs[32][65];  // [c2_local][k]
    const int t = threadIdx.x;
    const int c2_0 = blockIdx.x * 32, c1_0 = blockIdx.y * 32, kk = blockIdx.z * 64;
    #pragma unroll
    for (int q = 0; q < 2; ++q) {
        int idx = t + q * 256;
        int r = idx >> 4, c4 = (idx & 15) * 4;
        float4 a = *(const float4*)&W1[(c1_0 + r) * 768 + kk + c4];
        A[r][c4] = a.x; A[r][c4 + 1] = a.y; A[r][c4 + 2] = a.z; A[r][c4 + 3] = a.w;
        float4 b = *(const float4*)&W2[(c2_0 + r) * 768 + 256 + kk + c4];
        Bs[r][c4] = b.x; Bs[r][c4 + 1] = b.y; Bs[r][c4 + 2] = b.z; Bs[r][c4 + 3] = b.w;
    }
    __syncthreads();
    const int ty = t >> 4, tx = t & 15;
    float a00 = 0.f, a01 = 0.f, a10 = 0.f, a11 = 0.f;
    #pragma unroll
    for (int k = 0; k < 64; ++k) {
        float x0 = A[ty * 2][k], x1 = A[ty * 2 + 1][k];
        float y0 = Bs[tx * 2][k], y1 = Bs[tx * 2 + 1][k];
        a00 += x0 * y0; a01 += x0 * y1; a10 += x1 * y0; a11 += x1 * y1;
    }
    atomicAdd(&g_M[(c1_0 + ty * 2)     * 256 + c2_0 + tx * 2],     a00);
    atomicAdd(&g_M[(c1_0 + ty * 2)     * 256 + c2_0 + tx * 2 + 1], a01);
    atomicAdd(&g_M[(c1_0 + ty * 2 + 1) * 256 + c2_0 + tx * 2],     a10);
    atomicAdd(&g_M[(c1_0 + ty * 2 + 1) * 256 + c2_0 + tx * 2 + 1], a11);
}

// ---------------- Kernel 2: U[b][c2][l] via mma.sync tf32 3x-split ----------------
// D[m=l(128)][n=c2(128)] = sum_k A[m][k] B[k][n]; A chunk = HSI[k][m] (native),
// B chunk = M[k][n] (native). cp.async double-buffered raw f32, split in regs.
#define PA 136                               // pitch (floats); PA % 32 == 8 -> conflict-free frags
#define CHUNK_F (32 * PA)                    // floats per A (or B) chunk buffer
#define K2_SMEM (2 * 2 * CHUNK_F * 4)        // 69632 B

__global__ __launch_bounds__(256) void k2_U(const float* __restrict__ HSI) {
    extern __shared__ float sm[];
    const int t = threadIdx.x, wid = t >> 5, lane = t & 31;
    const int g = lane >> 2, t4 = lane & 3;
    const int b = blockIdx.z, c2_0 = blockIdx.y * 128, l0 = blockIdx.x * 128;
    const int mw = (wid >> 1) * 32, nw = (wid & 1) * 64;
    const float* Hb = HSI + (size_t)b * C_DIM * L_DIM;

    const uint32_t sbase = smem_u32(sm);
    const int cprow = t >> 5, cpquad = t & 31;    // copy mapping: 8 rows x 32 quads per pass

    float d[2][8][4];
    #pragma unroll
    for (int mt = 0; mt < 2; ++mt)
        #pragma unroll
        for (int nt = 0; nt < 8; ++nt)
            #pragma unroll
            for (int i = 0; i < 4; ++i) d[mt][nt][i] = 0.f;

    // issue chunk 0
    {
        float* A0 = sm; float* B0 = sm + CHUNK_F;
        #pragma unroll
        for (int q = 0; q < 4; ++q) {
            int r = cprow + q * 8;
            cp16(sbase + (uint32_t)((A0 - sm + r * PA + cpquad * 4) * 4),
                 &Hb[(size_t)r * L_DIM + l0 + cpquad * 4]);
            cp16(sbase + (uint32_t)((B0 - sm + r * PA + cpquad * 4) * 4),
                 &g_M[r * 256 + c2_0 + cpquad * 4]);
        }
        cp_commit();
    }

    for (int ch = 0; ch < 8; ++ch) {
        if (ch < 7) {
            int p = (ch + 1) & 1;
            int kk = (ch + 1) * 32;
            float* Ab = sm + p * 2 * CHUNK_F;
            float* Bb = Ab + CHUNK_F;
            #pragma unroll
            for (int q = 0; q < 4; ++q) {
                int r = cprow + q * 8;
                cp16(sbase + (uint32_t)((Ab - sm + r * PA + cpquad * 4) * 4),
                     &Hb[(size_t)(kk + r) * L_DIM + l0 + cpquad * 4]);
                cp16(sbase + (uint32_t)((Bb - sm + r * PA + cpquad * 4) * 4),
                     &g_M[(kk + r) * 256 + c2_0 + cpquad * 4]);
            }
            cp_commit();
            cp_wait<1>();
        } else {
            cp_wait<0>();
        }
        __syncthreads();

        const float* As = sm + (ch & 1) * 2 * CHUNK_F;
        const float* Bs = As + CHUNK_F;

        #pragma unroll
        for (int s = 0; s < 4; ++s) {
            const int r0 = 8 * s + t4, r1 = r0 + 4;
            // A fragments (2 m-tiles), split hi/lo in regs
            uint32_t ah[2][4], al[2][4];
            #pragma unroll
            for (int mt = 0; mt < 2; ++mt) {
                int m0 = mw + 16 * mt + g;
                float v0 = As[r0 * PA + m0];
                float v1 = As[r0 * PA + m0 + 8];
                float v2 = As[r1 * PA + m0];
                float v3 = As[r1 * PA + m0 + 8];
                ah[mt][0] = tf32_hi(v0); al[mt][0] = tf32_lo(v0, ah[mt][0]);
                ah[mt][1] = tf32_hi(v1); al[mt][1] = tf32_lo(v1, ah[mt][1]);
                ah[mt][2] = tf32_hi(v2); al[mt][2] = tf32_lo(v2, ah[mt][2]);
                ah[mt][3] = tf32_hi(v3); al[mt][3] = tf32_lo(v3, ah[mt][3]);
            }
            // B fragments (8 n-tiles)
            uint32_t bh[8][2], bl[8][2];
            #pragma unroll
            for (int nt = 0; nt < 8; ++nt) {
                int n0 = nw + 8 * nt + g;
                float v0 = Bs[r0 * PA + n0];
                float v1 = Bs[r1 * PA + n0];
                bh[nt][0] = tf32_hi(v0); bl[nt][0] = tf32_lo(v0, bh[nt][0]);
                bh[nt][1] = tf32_hi(v1); bl[nt][1] = tf32_lo(v1, bh[nt][1]);
            }
            // 3 split terms, 16 independent tiles each (ample ILP)
            #pragma unroll
            for (int mt = 0; mt < 2; ++mt)
                #pragma unroll
                for (int nt = 0; nt < 8; ++nt)
                    mma8(d[mt][nt], ah[mt], bh[nt]);
            #pragma unroll
            for (int mt = 0; mt < 2; ++mt)
                #pragma unroll
                for (int nt = 0; nt < 8; ++nt)
                    mma8(d[mt][nt], ah[mt], bl[nt]);
            #pragma unroll
            for (int mt = 0; mt < 2; ++mt)
                #pragma unroll
                for (int nt = 0; nt < 8; ++nt)
                    mma8(d[mt][nt], al[mt], bh[nt]);
        }
        __syncthreads();
    }

    // epilogue: D row -> l, col -> c2 ; U[c2][l]
    float* Ub = g_U + (size_t)b * C_DIM * L_DIM;
    #pragma unroll
    for (int mt = 0; mt < 2; ++mt) {
        int row0 = l0 + mw + 16 * mt + g;
        #pragma unroll
        for (int nt = 0; nt < 8; ++nt) {
            int col0 = c2_0 + nw + 8 * nt + 2 * t4;
            Ub[(size_t)col0       * L_DIM + row0]     = d[mt][nt][0];
            Ub[(size_t)(col0 + 1) * L_DIM + row0]     = d[mt][nt][1];
            Ub[(size_t)col0       * L_DIM + row0 + 8] = d[mt][nt][2];
            Ub[(size_t)(col0 + 1) * L_DIM + row0 + 8] = d[mt][nt][3];
        }
    }
}

// ---------------- Kernel 3: scores + argmax -> offsets ----------------
__global__ __launch_bounds__(288) void k3_attn(const float* __restrict__ MSI,
                                               float* __restrict__ out) {
    __shared__ __align__(16) float us[256][33];
    __shared__ float sc[288];
    const int t = threadIdx.x;
    const int b = blockIdx.y;
    const int l0 = blockIdx.x * 32;
    const int m0 = blockIdx.x * 288;
    const float* Mb = MSI + (size_t)b * C_DIM * LM_DIM;
    const float* Ub = g_U + (size_t)b * C_DIM * L_DIM;

    for (int i = t; i < 256 * 32; i += 288) {
        int c2 = i >> 5, l = i & 31;
        us[c2][l] = Ub[(size_t)c2 * L_DIM + l0 + l];
    }
    __syncthreads();

    const int m = m0 + t;
    const int ll = t / 9;
    const float* mp = Mb + m;
    float acc = 0.f;
    #pragma unroll 8
    for (int c2 = 0; c2 < 256; ++c2)
        acc += us[c2][ll] * mp[c2 * LM_DIM];
    sc[t] = acc;
    __syncthreads();

    if (t < 32) {
        float best = sc[t * 9];
        int bn = 0;
        #pragma unroll
        for (int j = 1; j < 9; ++j) {
            float v = sc[t * 9 + j];
            if (v > best) { best = v; bn = j; }   // strict > keeps first max (jnp.argmax)
        }
        float2 o = make_float2((float)(bn / 3) - 1.f, (float)(bn % 3) - 1.f);
        *(float2*)&out[(size_t)(b * L_DIM + l0 + t) * 2] = o;
    }
}

// ---------------- launch ----------------
extern "C" void kernel_launch(void* const* d_in, const int* in_sizes, int n_in,
                              void* d_out, int out_size) {
    const float* HSI = (const float*)d_in[2];
    const float* MSI = (const float*)d_in[3];
    const float* W1  = (const float*)d_in[4];
    const float* W2  = (const float*)d_in[5];
    float* out = (float*)d_out;

    void* mp = nullptr;
    cudaGetSymbolAddress(&mp, g_M);
    cudaMemsetAsync(mp, 0, C_DIM * C_DIM * sizeof(float), 0);

    k1_M<<<dim3(8, 8, 4), 256>>>(W1, W2);

    cudaFuncSetAttribute(k2_U, cudaFuncAttributeMaxDynamicSharedMemorySize, K2_SMEM);
    k2_U<<<dim3(32, 2, 4), 256, K2_SMEM>>>(HSI);

    k3_attn<<<dim3(128, 4), 288>>>(MSI, out);
}